// round 14
// baseline (speedup 1.0000x reference)
#include <cuda_runtime.h>
#include <cuda_fp16.h>
#include <cstdint>
#include <cstddef>

// Problem constants (B=4, H=16, S=2048, D=64)
#define S_LEN   2048
#define D_DIM   64
#define BH      64
#define M_BLK   128
#define KT      64
#define NT      (S_LEN/KT)
#define NTHREADS 256

#define RH      72                    // padded halves per K/V row (36 words)
#define KTILE_B (KT*RH*2)             // 9216 B per K/V tile (contiguous in gmem)
#define MSTR    68                    // int32 words per mask-tile row (272 B)
#define MTILE_B (M_BLK*MSTR*4)        // 34816 B per mask tile (single stage)

// smem byte offsets: K db 18432 + V db 18432 + mask 34816 + mbars
#define OFF_K   0
#define OFF_V   (OFF_K + 2*KTILE_B)   // 18432
#define OFF_M   (OFF_V + 2*KTILE_B)   // 36864
#define OFF_MB  (OFF_M + MTILE_B)     // 71680: 3 mbarriers (kv0, kv1, mask)
#define SMEM_BYTES (OFF_MB + 24)      // 71704 -> 3 CTAs/SM
#define KV_TX   (2*KTILE_B)           // 18432 per K/V stage
#define M_TX    (M_BLK*256)           // 32768 per mask tile

__device__ __half   g_Kh[(size_t)BH*S_LEN*RH];      // [bh][key][72] fp16, fragment-permuted
__device__ __half   g_Vt[(size_t)BH*S_LEN*RH];      // [bh][kt][d][72] fp16, fragment-permuted
__device__ uint32_t g_Eh[(size_t)BH*S_LEN*S_LEN/2]; // packed-half2 e scratch
__device__ int      g_mask_kind;      // 0 = 1B/elem, 1 = 4B/elem

__global__ void detect_mask_kind(const unsigned char* __restrict__ m) {
    __shared__ int s_big, s_off;
    if (threadIdx.x == 0) { s_big = 0; s_off = 0; }
    __syncthreads();
    int big = 0, off = 0;
    for (int base = threadIdx.x * 16; base < 4096; base += 256 * 16) {
        uint4 v = *(const uint4*)(m + base);
        unsigned int w[4] = {v.x, v.y, v.z, v.w};
#pragma unroll
        for (int j = 0; j < 4; j++)
#pragma unroll
            for (int b = 0; b < 4; b++) {
                unsigned int byte = (w[j] >> (8 * b)) & 0xFFu;
                if (byte > 1u) big = 1;
                if (byte != 0u && (((base + 4 * j + b) & 3) != 0)) off = 1;
            }
    }
    if (big) atomicOr(&s_big, 1);
    if (off) atomicOr(&s_off, 1);
    __syncthreads();
    if (threadIdx.x == 0) g_mask_kind = (s_big || !s_off) ? 1 : 0;
}

// fallback only (byte masks): widen u8 -> int32 into the attn buffer (same offsets).
__global__ void widen_mask_u8(const unsigned char* __restrict__ M, int* __restrict__ dst) {
    if (g_mask_kind != 0) return;
    const size_t n = (size_t)BH * S_LEN * S_LEN / 4;
    size_t i = (size_t)blockIdx.x * blockDim.x + threadIdx.x;
    const size_t stride = (size_t)gridDim.x * blockDim.x;
    for (; i < n; i += stride) {
        uchar4 v = ((const uchar4*)M)[i];
        ((int4*)dst)[i] = make_int4(v.x, v.y, v.z, v.w);
    }
}

// fragment permutation: position p = t*8 + 2*kc + h holds source word 8*kc + t + 4*h
__device__ __forceinline__ int frag_pos(int w) {
    int kc = w >> 3, rem = w & 7;
    int h = rem >> 2, t = rem & 3;
    return t * 8 + 2 * kc + h;
}

__global__ void convert_k(const float* __restrict__ K) {
    const size_t nw = (size_t)BH * S_LEN * 32;
    size_t i = (size_t)blockIdx.x * blockDim.x + threadIdx.x;
    const size_t stride = (size_t)gridDim.x * blockDim.x;
    for (; i < nw; i += stride) {
        size_t row = i >> 5;
        int w = (int)(i & 31);
        float2 v = *(const float2*)(K + row * 64 + 2 * w);
        ((__half2*)g_Kh)[row * 36 + frag_pos(w)] = __floats2half2_rn(v.x, v.y);
    }
}

__global__ void transpose_v(const float* __restrict__ V) {
    __shared__ float vs[KT][D_DIM + 1];
    const int kt = blockIdx.x, bh = blockIdx.y;
    const float* src = V + ((size_t)bh * S_LEN + kt * KT) * D_DIM;
    const int tid = threadIdx.x;
    for (int i = tid * 4; i < KT * D_DIM; i += NTHREADS * 4) {
        float4 v = *(const float4*)(src + i);
        int r = i >> 6, c = i & 63;
        vs[r][c] = v.x; vs[r][c+1] = v.y; vs[r][c+2] = v.z; vs[r][c+3] = v.w;
    }
    __syncthreads();
    __half2* dst = (__half2*)(g_Vt + ((size_t)bh * NT + kt) * (KT * RH));
    for (int i = tid; i < KT * 32; i += NTHREADS) {
        int d = i >> 5, kp = i & 31;
        dst[d * 36 + frag_pos(kp)] = __floats2half2_rn(vs[2*kp][d], vs[2*kp+1][d]);
    }
}

__device__ __forceinline__ void mma_f16(float c[4],
                                        uint32_t a0, uint32_t a1, uint32_t a2, uint32_t a3,
                                        uint32_t b0, uint32_t b1) {
    asm volatile(
        "mma.sync.aligned.m16n8k16.row.col.f32.f16.f16.f32 "
        "{%0,%1,%2,%3}, {%4,%5,%6,%7}, {%8,%9}, {%0,%1,%2,%3};\n"
        : "+f"(c[0]), "+f"(c[1]), "+f"(c[2]), "+f"(c[3])
        : "r"(a0), "r"(a1), "r"(a2), "r"(a3), "r"(b0), "r"(b1));
}

__device__ __forceinline__ uint32_t pack_h2(float lo, float hi) {
    __half2 h = __floats2half2_rn(lo, hi);
    return *(uint32_t*)&h;
}

__device__ __forceinline__ void mbar_init(uint32_t mbar, uint32_t count) {
    asm volatile("mbarrier.init.shared.b64 [%0], %1;" :: "r"(mbar), "r"(count) : "memory");
}
__device__ __forceinline__ void mbar_expect_tx(uint32_t mbar, uint32_t bytes) {
    asm volatile("mbarrier.arrive.expect_tx.shared.b64 _, [%0], %1;"
                 :: "r"(mbar), "r"(bytes) : "memory");
}
__device__ __forceinline__ void bulk_g2s(uint32_t dst, const void* src, uint32_t bytes, uint32_t mbar) {
    asm volatile("cp.async.bulk.shared::cluster.global.mbarrier::complete_tx::bytes "
                 "[%0], [%1], %2, [%3];"
                 :: "r"(dst), "l"(src), "r"(bytes), "r"(mbar) : "memory");
}
__device__ __forceinline__ void mbar_wait(uint32_t mbar, uint32_t parity) {
    asm volatile(
        "{\n\t.reg .pred P1;\n\t"
        "WAIT_%=:\n\t"
        "mbarrier.try_wait.parity.shared.b64 P1, [%0], %1;\n\t"
        "@P1 bra DONE_%=;\n\t"
        "bra WAIT_%=;\n\t"
        "DONE_%=:\n\t}"
        :: "r"(mbar), "r"(parity) : "memory");
}

__global__ void __launch_bounds__(NTHREADS, 3)
sdpa_main(const float* __restrict__ Q, const unsigned char* __restrict__ M,
          float* __restrict__ ctx, float* __restrict__ attn) {
    extern __shared__ __half smh[];
    uint32_t smb;
    asm("{ .reg .u64 tmp; cvta.to.shared.u64 tmp, %1; cvt.u32.u64 %0, tmp; }"
        : "=r"(smb) : "l"(smh));

    const int qb = blockIdx.x;            // 0..15
    const int bh = blockIdx.y;            // 0..63
    const size_t mrow0 = (size_t)bh * S_LEN + qb * M_BLK;

    const int tid = threadIdx.x, warp = tid >> 5, lane = tid & 31;
    const int g = lane >> 2, t = lane & 3;
    const int r0 = 16 * warp;

    const int* msrc = (g_mask_kind != 0) ? (const int*)M : (const int*)attn;
    const __half* gK = g_Kh + (size_t)bh * S_LEN * RH;
    const __half* gV = g_Vt + (size_t)bh * S_LEN * RH;

    // ---- mbarrier init: kv stage 0/1, mask ----
    if (tid == 0) {
        mbar_init(smb + OFF_MB, 1);
        mbar_init(smb + OFF_MB + 8, 1);
        mbar_init(smb + OFF_MB + 16, 1);
        asm volatile("fence.proxy.async.shared::cta;" ::: "memory");
    }
    __syncthreads();

    auto issue_kv = [&](int stage, int tile) {
        uint32_t mbar = smb + OFF_MB + stage * 8;
        if (tid == 0) {
            mbar_expect_tx(mbar, KV_TX);
            bulk_g2s(smb + OFF_K + stage * KTILE_B, gK + (size_t)tile * KT * RH, KTILE_B, mbar);
        } else if (tid == 32) {
            bulk_g2s(smb + OFF_V + stage * KTILE_B, gV + (size_t)tile * KT * RH, KTILE_B, mbar);
        }
    };
    auto issue_mask = [&](int tile) {
        uint32_t mbar = smb + OFF_MB + 16;
        if (tid == 0) mbar_expect_tx(mbar, M_TX);
        if (tid < 128)
            bulk_g2s(smb + OFF_M + tid * 272,
                     msrc + (mrow0 + tid) * S_LEN + tile * KT, 256, mbar);
    };

    // ---- Q fragments straight from gmem (once) ----
    uint32_t qa[4][4];
    {
        const float* Qp = Q + mrow0 * D_DIM;
#pragma unroll
        for (int kc = 0; kc < 4; kc++) {
            float2 v0 = *(const float2*)(Qp + (r0 + g)     * D_DIM + 16 * kc + 2 * t);
            float2 v1 = *(const float2*)(Qp + (r0 + g + 8) * D_DIM + 16 * kc + 2 * t);
            float2 v2 = *(const float2*)(Qp + (r0 + g)     * D_DIM + 16 * kc + 2 * t + 8);
            float2 v3 = *(const float2*)(Qp + (r0 + g + 8) * D_DIM + 16 * kc + 2 * t + 8);
            qa[kc][0] = pack_h2(v0.x, v0.y);
            qa[kc][1] = pack_h2(v1.x, v1.y);
            qa[kc][2] = pack_h2(v2.x, v2.y);
            qa[kc][3] = pack_h2(v3.x, v3.y);
        }
    }

    // ---- prologue: K/V tiles 0,1 and mask tile 0 ----
    issue_kv(0, 0);
    issue_kv(1, 1);
    issue_mask(0);

    const size_t tb_warp = (((size_t)(bh * 16 + qb) * 8 + warp) * 32) * 512;

    float acc[8][4] = {};
    float rs0 = 0.f, rs1 = 0.f;

    for (int kt = 0; kt < NT; kt++) {
        const int cur = kt & 1;
        mbar_wait(smb + OFF_MB + cur * 8, (kt >> 1) & 1);   // K/V stage ready
        mbar_wait(smb + OFF_MB + 16, kt & 1);               // mask tile ready

        const uint32_t* Kw = (const uint32_t*)(smh + (OFF_K + cur * KTILE_B) / 2);
        const uint32_t* Vw = (const uint32_t*)(smh + (OFF_V + cur * KTILE_B) / 2);
        const int*      Mb = (const int*)(smh + OFF_M / 2);

        // ---- QK (nb-outer): 2 LDS.128 + 4 mma per nb ----
        uint32_t pw[16];
        const float scale = 0.125f;
#pragma unroll
        for (int nb = 0; nb < 8; nb++) {
            const uint32_t* rowp = Kw + (8 * nb + g) * 36 + t * 8;
            uint4 k0 = *(const uint4*)rowp;
            uint4 k1 = *(const uint4*)(rowp + 4);
            float cl[4] = {};
            mma_f16(cl, qa[0][0], qa[0][1], qa[0][2], qa[0][3], k0.x, k0.y);
            mma_f16(cl, qa[1][0], qa[1][1], qa[1][2], qa[1][3], k0.z, k0.w);
            mma_f16(cl, qa[2][0], qa[2][1], qa[2][2], qa[2][3], k1.x, k1.y);
            mma_f16(cl, qa[3][0], qa[3][1], qa[3][2], qa[3][3], k1.z, k1.w);

            int2 ma = *(const int2*)&Mb[(r0 + g)     * MSTR + 8 * nb + 2 * t];
            int2 mb = *(const int2*)&Mb[(r0 + g + 8) * MSTR + 8 * nb + 2 * t];
            float e0 = ma.x ? 0.f : __expf(cl[0] * scale);
            float e1 = ma.y ? 0.f : __expf(cl[1] * scale);
            float e2 = mb.x ? 0.f : __expf(cl[2] * scale);
            float e3 = mb.y ? 0.f : __expf(cl[3] * scale);
            rs0 += e0 + e1; rs1 += e2 + e3;
            pw[2 * nb]     = pack_h2(e0, e1);
            pw[2 * nb + 1] = pack_h2(e2, e3);
        }

        // ---- scratch store: 4 x STG.128 ----
        {
            uint4* sp4 = (uint4*)(g_Eh + tb_warp + (size_t)kt * 512);
#pragma unroll
            for (int w4 = 0; w4 < 4; w4++)
                sp4[w4 * 32 + lane] = make_uint4(pw[4*w4], pw[4*w4+1], pw[4*w4+2], pw[4*w4+3]);
        }

        // ---- PV: 2 LDS.128 + 4 mma per db ----
#pragma unroll
        for (int db = 0; db < 8; db++) {
            const uint32_t* rowp = Vw + (8 * db + g) * 36 + t * 8;
            uint4 v0 = *(const uint4*)rowp;
            uint4 v1 = *(const uint4*)(rowp + 4);
            mma_f16(acc[db], pw[0],  pw[1],  pw[2],  pw[3],  v0.x, v0.y);
            mma_f16(acc[db], pw[4],  pw[5],  pw[6],  pw[7],  v0.z, v0.w);
            mma_f16(acc[db], pw[8],  pw[9],  pw[10], pw[11], v1.x, v1.y);
            mma_f16(acc[db], pw[12], pw[13], pw[14], pw[15], v1.z, v1.w);
        }

        __syncthreads();                  // all warps done with KV stage cur + mask tile kt
        if (kt + 2 < NT) issue_kv(cur, kt + 2);
        if (kt + 1 < NT) issue_mask(kt + 1);
    }

    // ---- rowsums -> 1/Z ----
    rs0 += __shfl_xor_sync(0xFFFFFFFFu, rs0, 1);
    rs0 += __shfl_xor_sync(0xFFFFFFFFu, rs0, 2);
    rs1 += __shfl_xor_sync(0xFFFFFFFFu, rs1, 1);
    rs1 += __shfl_xor_sync(0xFFFFFFFFu, rs1, 2);
    const float iv0 = 1.f / rs0, iv1 = 1.f / rs1;

    // ---- context = acc / Z ----
    {
        float* cpa = ctx + (mrow0 + r0 + g) * D_DIM + 2 * t;
        float* cpb = cpa + 8 * D_DIM;
#pragma unroll
        for (int db = 0; db < 8; db++) {
            *(float2*)(cpa + 8 * db) = make_float2(acc[db][0] * iv0, acc[db][1] * iv0);
            *(float2*)(cpb + 8 * db) = make_float2(acc[db][2] * iv1, acc[db][3] * iv1);
        }
    }

    // ---- expand: scratch -> normalized fp32 attn, coalesced ----
    __syncthreads();
    uint32_t* stg = (uint32_t*)smh;       // 8 warps x 544 words (padded transpose)
    float* sinv = (float*)((uint32_t*)smh + 8 * 544);
    if (t == 0) {
        sinv[r0 + g]     = iv0;
        sinv[r0 + g + 8] = iv1;
    }
    __syncthreads();

    const size_t tb_cta = ((size_t)(bh * 16 + qb) * 8) * 32 * 512;
    for (int kt = 0; kt < NT; kt++) {
        const uint4* src4 = (const uint4*)(g_Eh + tb_cta + (size_t)(warp * 32 + kt) * 512);
#pragma unroll
        for (int w4 = 0; w4 < 4; w4++) {
            uint4 v = src4[w4 * 32 + lane];
            stg[warp * 544 + lane * 17 + 4 * w4 + 0] = v.x;
            stg[warp * 544 + lane * 17 + 4 * w4 + 1] = v.y;
            stg[warp * 544 + lane * 17 + 4 * w4 + 2] = v.z;
            stg[warp * 544 + lane * 17 + 4 * w4 + 3] = v.w;
        }
        __syncthreads();

#pragma unroll
        for (int it = 0; it < 8; it++) {
            int o = it * 256 + tid;
            int row = o >> 4;
            int cq  = o & 15;
            int wr = row >> 4, r = row & 15, gg = r & 7, p = r >> 3;
            int c0 = cq * 4;
            int nb = c0 >> 3;
            int t0 = (c0 & 7) >> 1;
            uint32_t w1 = stg[wr * 544 + (gg * 4 + t0)     * 17 + 2 * nb + p];
            uint32_t w2 = stg[wr * 544 + (gg * 4 + t0 + 1) * 17 + 2 * nb + p];
            float iv = sinv[row];
            __half2 h1 = *(__half2*)&w1, h2 = *(__half2*)&w2;
            float4 out = make_float4(__low2float(h1) * iv, __high2float(h1) * iv,
                                     __low2float(h2) * iv, __high2float(h2) * iv);
            *(float4*)(attn + (mrow0 + row) * S_LEN + kt * KT + c0) = out;
        }
        __syncthreads();
    }
}

extern "C" void kernel_launch(void* const* d_in, const int* in_sizes, int n_in,
                              void* d_out, int out_size) {
    const float* Q = (const float*)d_in[0];
    const float* K = (const float*)d_in[1];
    const float* V = (const float*)d_in[2];
    const unsigned char* M = (const unsigned char*)d_in[3];

    float* ctx  = (float*)d_out;                          // [B,H,S,64]
    float* attn = ctx + (size_t)BH * S_LEN * D_DIM;       // [B,H,S,S]

    cudaFuncSetAttribute(sdpa_main,
                         cudaFuncAttributeMaxDynamicSharedMemorySize, SMEM_BYTES);

    detect_mask_kind<<<1, 256>>>(M);
    widen_mask_u8<<<4096, 256>>>(M, (int*)attn);   // no-op when mask is 4B/elem
    convert_k<<<2048, 256>>>(K);
    transpose_v<<<dim3(NT, BH), 256>>>(V);

    dim3 grid(S_LEN / M_BLK, BH);                         // 16 x 64 = 1024 CTAs
    sdpa_main<<<grid, NTHREADS, SMEM_BYTES>>>(Q, M, ctx, attn);
}

// round 15
// speedup vs baseline: 1.2138x; 1.2138x over previous
#include <cuda_runtime.h>
#include <cuda_fp16.h>
#include <cstdint>
#include <cstddef>

// Problem constants (B=4, H=16, S=2048, D=64)
#define S_LEN   2048
#define D_DIM   64
#define BH      64
#define M_BLK   128
#define KT      64
#define NT      (S_LEN/KT)
#define NTHREADS 256

#define RH      72                    // padded halves per K/V row (36 words)
#define KTILE_B (KT*RH*2)             // 9216 B per K/V tile (contiguous in gmem)
#define MSTR    68                    // int32 words per mask-tile row (272 B)
#define MTILE_B (M_BLK*MSTR*4)        // 34816 B per mask tile

// smem byte offsets
#define OFF_K   0                     // 2 x 9216
#define OFF_V   (OFF_K + 2*KTILE_B)   // 18432: 2 x 9216
#define OFF_M   (OFF_V + 2*KTILE_B)   // 36864: 2 x 34816
#define OFF_MB  (OFF_M + 2*MTILE_B)   // 106496: 2 mbarriers
#define SMEM_BYTES (OFF_MB + 16)
#define TX_BYTES (KTILE_B + KTILE_B + M_BLK*256)   // 51200 per stage

__device__ __half   g_Kh[(size_t)BH*S_LEN*RH];      // [bh][key][72] fp16, fragment-permuted
__device__ __half   g_Vt[(size_t)BH*S_LEN*RH];      // [bh][kt][d][72] fp16, fragment-permuted
__device__ uint32_t g_Eh[(size_t)BH*S_LEN*S_LEN/2]; // packed-half2 e scratch
__device__ int      g_mask_kind;      // 0 = 1B/elem, 1 = 4B/elem

__global__ void detect_mask_kind(const unsigned char* __restrict__ m) {
    __shared__ int s_big, s_off;
    if (threadIdx.x == 0) { s_big = 0; s_off = 0; }
    __syncthreads();
    int big = 0, off = 0;
    for (int base = threadIdx.x * 16; base < 4096; base += 256 * 16) {
        uint4 v = *(const uint4*)(m + base);
        unsigned int w[4] = {v.x, v.y, v.z, v.w};
#pragma unroll
        for (int j = 0; j < 4; j++)
#pragma unroll
            for (int b = 0; b < 4; b++) {
                unsigned int byte = (w[j] >> (8 * b)) & 0xFFu;
                if (byte > 1u) big = 1;
                if (byte != 0u && (((base + 4 * j + b) & 3) != 0)) off = 1;
            }
    }
    if (big) atomicOr(&s_big, 1);
    if (off) atomicOr(&s_off, 1);
    __syncthreads();
    if (threadIdx.x == 0) g_mask_kind = (s_big || !s_off) ? 1 : 0;
}

// fallback only (byte masks): widen u8 -> int32 into the attn buffer (same offsets).
__global__ void widen_mask_u8(const unsigned char* __restrict__ M, int* __restrict__ dst) {
    if (g_mask_kind != 0) return;
    const size_t n = (size_t)BH * S_LEN * S_LEN / 4;
    size_t i = (size_t)blockIdx.x * blockDim.x + threadIdx.x;
    const size_t stride = (size_t)gridDim.x * blockDim.x;
    for (; i < n; i += stride) {
        uchar4 v = ((const uchar4*)M)[i];
        ((int4*)dst)[i] = make_int4(v.x, v.y, v.z, v.w);
    }
}

// fragment permutation: position p = t*8 + 2*kc + h holds source word 8*kc + t + 4*h
__device__ __forceinline__ int frag_pos(int w) {
    int kc = w >> 3, rem = w & 7;
    int h = rem >> 2, t = rem & 3;
    return t * 8 + 2 * kc + h;
}

// fused prepass: K -> fp16 fragment-permuted rows; V -> fp16 per-tile transposed
__global__ void prep_kv(const float* __restrict__ K, const float* __restrict__ V) {
    __shared__ float vs[KT][D_DIM + 1];
    const int kt = blockIdx.x, bh = blockIdx.y;
    const int tid = threadIdx.x;
    const size_t row0 = (size_t)bh * S_LEN + kt * KT;

    // ---- K convert (64 rows of this tile) ----
    {
        const float* ksrc = K + row0 * D_DIM;
        __half2* kdst = (__half2*)(g_Kh + row0 * RH);
        for (int i = tid; i < KT * 32; i += NTHREADS) {
            int r = i >> 5, w = i & 31;
            float2 v = *(const float2*)(ksrc + r * D_DIM + 2 * w);
            kdst[r * 36 + frag_pos(w)] = __floats2half2_rn(v.x, v.y);
        }
    }

    // ---- V transpose ----
    const float* src = V + row0 * D_DIM;
    for (int i = tid * 4; i < KT * D_DIM; i += NTHREADS * 4) {
        float4 v = *(const float4*)(src + i);
        int r = i >> 6, c = i & 63;
        vs[r][c] = v.x; vs[r][c+1] = v.y; vs[r][c+2] = v.z; vs[r][c+3] = v.w;
    }
    __syncthreads();
    __half2* dst = (__half2*)(g_Vt + ((size_t)bh * NT + kt) * (KT * RH));
    for (int i = tid; i < KT * 32; i += NTHREADS) {
        int d = i >> 5, kp = i & 31;
        dst[d * 36 + frag_pos(kp)] = __floats2half2_rn(vs[2*kp][d], vs[2*kp+1][d]);
    }
}

__device__ __forceinline__ void mma_f16(float c[4],
                                        uint32_t a0, uint32_t a1, uint32_t a2, uint32_t a3,
                                        uint32_t b0, uint32_t b1) {
    asm volatile(
        "mma.sync.aligned.m16n8k16.row.col.f32.f16.f16.f32 "
        "{%0,%1,%2,%3}, {%4,%5,%6,%7}, {%8,%9}, {%0,%1,%2,%3};\n"
        : "+f"(c[0]), "+f"(c[1]), "+f"(c[2]), "+f"(c[3])
        : "r"(a0), "r"(a1), "r"(a2), "r"(a3), "r"(b0), "r"(b1));
}

__device__ __forceinline__ uint32_t pack_h2(float lo, float hi) {
    __half2 h = __floats2half2_rn(lo, hi);
    return *(uint32_t*)&h;
}

__device__ __forceinline__ void mbar_init(uint32_t mbar, uint32_t count) {
    asm volatile("mbarrier.init.shared.b64 [%0], %1;" :: "r"(mbar), "r"(count) : "memory");
}
__device__ __forceinline__ void mbar_expect_tx(uint32_t mbar, uint32_t bytes) {
    asm volatile("mbarrier.arrive.expect_tx.shared.b64 _, [%0], %1;"
                 :: "r"(mbar), "r"(bytes) : "memory");
}
__device__ __forceinline__ void bulk_g2s(uint32_t dst, const void* src, uint32_t bytes, uint32_t mbar) {
    asm volatile("cp.async.bulk.shared::cluster.global.mbarrier::complete_tx::bytes "
                 "[%0], [%1], %2, [%3];"
                 :: "r"(dst), "l"(src), "r"(bytes), "r"(mbar) : "memory");
}
__device__ __forceinline__ void mbar_wait(uint32_t mbar, uint32_t parity) {
    asm volatile(
        "{\n\t.reg .pred P1;\n\t"
        "WAIT_%=:\n\t"
        "mbarrier.try_wait.parity.shared.b64 P1, [%0], %1;\n\t"
        "@P1 bra DONE_%=;\n\t"
        "bra WAIT_%=;\n\t"
        "DONE_%=:\n\t}"
        :: "r"(mbar), "r"(parity) : "memory");
}

__global__ void __launch_bounds__(NTHREADS, 2)
sdpa_main(const float* __restrict__ Q, const unsigned char* __restrict__ M,
          float* __restrict__ ctx, float* __restrict__ attn) {
    extern __shared__ __half smh[];
    uint32_t smb;
    asm("{ .reg .u64 tmp; cvta.to.shared.u64 tmp, %1; cvt.u32.u64 %0, tmp; }"
        : "=r"(smb) : "l"(smh));

    const int qb = blockIdx.x;            // 0..15
    const int bh = blockIdx.y;            // 0..63
    const size_t mrow0 = (size_t)bh * S_LEN + qb * M_BLK;

    const int tid = threadIdx.x, warp = tid >> 5, lane = tid & 31;
    const int g = lane >> 2, t = lane & 3;
    const int r0 = 16 * warp;

    const int* msrc = (g_mask_kind != 0) ? (const int*)M : (const int*)attn;
    const __half* gK = g_Kh + (size_t)bh * S_LEN * RH;
    const __half* gV = g_Vt + (size_t)bh * S_LEN * RH;

    // ---- mbarrier init ----
    if (tid == 0) {
        mbar_init(smb + OFF_MB, 1);
        mbar_init(smb + OFF_MB + 8, 1);
        asm volatile("fence.proxy.async.shared::cta;" ::: "memory");
    }
    __syncthreads();

    // producer: issue one tile's bulk copies into stage s (mask rows first: largest payload)
    auto issue_tile = [&](int stage, int tile) {
        uint32_t mbar = smb + OFF_MB + stage * 8;
        if (tid == 0) mbar_expect_tx(mbar, TX_BYTES);
        if (tid < 128) {
            bulk_g2s(smb + OFF_M + stage * MTILE_B + tid * 272,
                     msrc + (mrow0 + tid) * S_LEN + tile * KT, 256, mbar);
        } else if (tid == 128) {
            bulk_g2s(smb + OFF_K + stage * KTILE_B, gK + (size_t)tile * KT * RH, KTILE_B, mbar);
        } else if (tid == 129) {
            bulk_g2s(smb + OFF_V + stage * KTILE_B, gV + (size_t)tile * KT * RH, KTILE_B, mbar);
        }
    };

    // ---- Q fragments straight from gmem (once) ----
    uint32_t qa[4][4];
    {
        const float* Qp = Q + mrow0 * D_DIM;
#pragma unroll
        for (int kc = 0; kc < 4; kc++) {
            float2 v0 = *(const float2*)(Qp + (r0 + g)     * D_DIM + 16 * kc + 2 * t);
            float2 v1 = *(const float2*)(Qp + (r0 + g + 8) * D_DIM + 16 * kc + 2 * t);
            float2 v2 = *(const float2*)(Qp + (r0 + g)     * D_DIM + 16 * kc + 2 * t + 8);
            float2 v3 = *(const float2*)(Qp + (r0 + g + 8) * D_DIM + 16 * kc + 2 * t + 8);
            qa[kc][0] = pack_h2(v0.x, v0.y);
            qa[kc][1] = pack_h2(v1.x, v1.y);
            qa[kc][2] = pack_h2(v2.x, v2.y);
            qa[kc][3] = pack_h2(v3.x, v3.y);
        }
    }

    // ---- prologue: tiles 0 and 1 ----
    issue_tile(0, 0);
    issue_tile(1, 1);

    const size_t tb_warp = (((size_t)(bh * 16 + qb) * 8 + warp) * 32) * 512;

    float acc[8][4] = {};
    float rs0 = 0.f, rs1 = 0.f;

    for (int kt = 0; kt < NT; kt++) {
        const int cur = kt & 1;
        mbar_wait(smb + OFF_MB + cur * 8, (kt >> 1) & 1);

        const uint32_t* Kw = (const uint32_t*)(smh + (OFF_K + cur * KTILE_B) / 2);
        const uint32_t* Vw = (const uint32_t*)(smh + (OFF_V + cur * KTILE_B) / 2);
        const int*      Mb = (const int*)(smh + (OFF_M + cur * MTILE_B) / 2);

        // ---- QK (nb-outer): 2 LDS.128 + 4 mma per nb ----
        uint32_t pw[16];
        const float scale = 0.125f;
#pragma unroll
        for (int nb = 0; nb < 8; nb++) {
            const uint32_t* rowp = Kw + (8 * nb + g) * 36 + t * 8;
            uint4 k0 = *(const uint4*)rowp;
            uint4 k1 = *(const uint4*)(rowp + 4);
            float cl[4] = {};
            mma_f16(cl, qa[0][0], qa[0][1], qa[0][2], qa[0][3], k0.x, k0.y);
            mma_f16(cl, qa[1][0], qa[1][1], qa[1][2], qa[1][3], k0.z, k0.w);
            mma_f16(cl, qa[2][0], qa[2][1], qa[2][2], qa[2][3], k1.x, k1.y);
            mma_f16(cl, qa[3][0], qa[3][1], qa[3][2], qa[3][3], k1.z, k1.w);

            int2 ma = *(const int2*)&Mb[(r0 + g)     * MSTR + 8 * nb + 2 * t];
            int2 mb = *(const int2*)&Mb[(r0 + g + 8) * MSTR + 8 * nb + 2 * t];
            float e0 = ma.x ? 0.f : __expf(cl[0] * scale);
            float e1 = ma.y ? 0.f : __expf(cl[1] * scale);
            float e2 = mb.x ? 0.f : __expf(cl[2] * scale);
            float e3 = mb.y ? 0.f : __expf(cl[3] * scale);
            rs0 += e0 + e1; rs1 += e2 + e3;
            pw[2 * nb]     = pack_h2(e0, e1);
            pw[2 * nb + 1] = pack_h2(e2, e3);
        }

        // ---- scratch store: 4 x STG.128 ----
        {
            uint4* sp4 = (uint4*)(g_Eh + tb_warp + (size_t)kt * 512);
#pragma unroll
            for (int w4 = 0; w4 < 4; w4++)
                sp4[w4 * 32 + lane] = make_uint4(pw[4*w4], pw[4*w4+1], pw[4*w4+2], pw[4*w4+3]);
        }

        // ---- PV: 2 LDS.128 + 4 mma per db ----
#pragma unroll
        for (int db = 0; db < 8; db++) {
            const uint32_t* rowp = Vw + (8 * db + g) * 36 + t * 8;
            uint4 v0 = *(const uint4*)rowp;
            uint4 v1 = *(const uint4*)(rowp + 4);
            mma_f16(acc[db], pw[0],  pw[1],  pw[2],  pw[3],  v0.x, v0.y);
            mma_f16(acc[db], pw[4],  pw[5],  pw[6],  pw[7],  v0.z, v0.w);
            mma_f16(acc[db], pw[8],  pw[9],  pw[10], pw[11], v1.x, v1.y);
            mma_f16(acc[db], pw[12], pw[13], pw[14], pw[15], v1.z, v1.w);
        }

        __syncthreads();                  // all warps done with buffer cur
        if (kt + 2 < NT) issue_tile(cur, kt + 2);
    }

    // ---- rowsums -> 1/Z ----
    rs0 += __shfl_xor_sync(0xFFFFFFFFu, rs0, 1);
    rs0 += __shfl_xor_sync(0xFFFFFFFFu, rs0, 2);
    rs1 += __shfl_xor_sync(0xFFFFFFFFu, rs1, 1);
    rs1 += __shfl_xor_sync(0xFFFFFFFFu, rs1, 2);
    const float iv0 = 1.f / rs0, iv1 = 1.f / rs1;

    // ---- context = acc / Z ----
    {
        float* cpa = ctx + (mrow0 + r0 + g) * D_DIM + 2 * t;
        float* cpb = cpa + 8 * D_DIM;
#pragma unroll
        for (int db = 0; db < 8; db++) {
            *(float2*)(cpa + 8 * db) = make_float2(acc[db][0] * iv0, acc[db][1] * iv0);
            *(float2*)(cpb + 8 * db) = make_float2(acc[db][2] * iv1, acc[db][3] * iv1);
        }
    }

    // ---- expand: scratch -> normalized fp32 attn; double-buffered staging,
    //      ONE sync per tile (read(kt) of buf A and write(kt+2) of buf A are
    //      separated by sync(kt+1)) ----
    __syncthreads();
    uint32_t* stg0 = (uint32_t*)smh;              // 2 x (8 warps x 544 words)
    float* sinv = (float*)((uint32_t*)smh + 2 * 8 * 544);
    if (t == 0) {
        sinv[r0 + g]     = iv0;
        sinv[r0 + g + 8] = iv1;
    }
    __syncthreads();

    const size_t tb_cta = ((size_t)(bh * 16 + qb) * 8) * 32 * 512;
    for (int kt = 0; kt < NT; kt++) {
        uint32_t* stg = stg0 + (kt & 1) * (8 * 544);
        const uint4* src4 = (const uint4*)(g_Eh + tb_cta + (size_t)(warp * 32 + kt) * 512);
#pragma unroll
        for (int w4 = 0; w4 < 4; w4++) {
            uint4 v = src4[w4 * 32 + lane];
            stg[warp * 544 + lane * 17 + 4 * w4 + 0] = v.x;
            stg[warp * 544 + lane * 17 + 4 * w4 + 1] = v.y;
            stg[warp * 544 + lane * 17 + 4 * w4 + 2] = v.z;
            stg[warp * 544 + lane * 17 + 4 * w4 + 3] = v.w;
        }
        __syncthreads();

#pragma unroll
        for (int it = 0; it < 8; it++) {
            int o = it * 256 + tid;
            int row = o >> 4;
            int cq  = o & 15;
            int wr = row >> 4, r = row & 15, gg = r & 7, p = r >> 3;
            int c0 = cq * 4;
            int nb = c0 >> 3;
            int t0 = (c0 & 7) >> 1;
            uint32_t w1 = stg[wr * 544 + (gg * 4 + t0)     * 17 + 2 * nb + p];
            uint32_t w2 = stg[wr * 544 + (gg * 4 + t0 + 1) * 17 + 2 * nb + p];
            float iv = sinv[row];
            __half2 h1 = *(__half2*)&w1, h2 = *(__half2*)&w2;
            float4 out = make_float4(__low2float(h1) * iv, __high2float(h1) * iv,
                                     __low2float(h2) * iv, __high2float(h2) * iv);
            *(float4*)(attn + (mrow0 + row) * S_LEN + kt * KT + c0) = out;
        }
    }
}

extern "C" void kernel_launch(void* const* d_in, const int* in_sizes, int n_in,
                              void* d_out, int out_size) {
    const float* Q = (const float*)d_in[0];
    const float* K = (const float*)d_in[1];
    const float* V = (const float*)d_in[2];
    const unsigned char* M = (const unsigned char*)d_in[3];

    float* ctx  = (float*)d_out;                          // [B,H,S,64]
    float* attn = ctx + (size_t)BH * S_LEN * D_DIM;       // [B,H,S,S]

    cudaFuncSetAttribute(sdpa_main,
                         cudaFuncAttributeMaxDynamicSharedMemorySize, SMEM_BYTES);

    detect_mask_kind<<<1, 256>>>(M);
    widen_mask_u8<<<4096, 256>>>(M, (int*)attn);   // no-op when mask is 4B/elem
    prep_kv<<<dim3(NT, BH), 256>>>(K, V);

    dim3 grid(S_LEN / M_BLK, BH);                         // 16 x 64 = 1024 CTAs
    sdpa_main<<<grid, NTHREADS, SMEM_BYTES>>>(Q, M, ctx, attn);
}

// round 16
// speedup vs baseline: 1.3373x; 1.1017x over previous
#include <cuda_runtime.h>
#include <cuda_fp16.h>
#include <cstdint>
#include <cstddef>

// Problem constants (B=4, H=16, S=2048, D=64)
#define S_LEN   2048
#define D_DIM   64
#define BH      64
#define M_BLK   128
#define KT      64
#define NT      (S_LEN/KT)
#define NTHREADS 256

#define RH      72                    // padded halves per K/V row (36 words)
#define KTILE_B (KT*RH*2)             // 9216 B per K/V tile (contiguous in gmem)
#define MSTR    68                    // int32 words per mask-tile row (272 B)
#define MTILE_B (M_BLK*MSTR*4)        // 34816 B per mask tile

// smem byte offsets
#define OFF_K   0                     // 2 x 9216
#define OFF_V   (OFF_K + 2*KTILE_B)   // 18432: 2 x 9216
#define OFF_M   (OFF_V + 2*KTILE_B)   // 36864: 2 x 34816
#define OFF_MB  (OFF_M + 2*MTILE_B)   // 106496: 2 mbarriers
#define SMEM_BYTES (OFF_MB + 16)
#define TX_BYTES (KTILE_B + KTILE_B + M_BLK*256)   // 51200 per stage

__device__ __half   g_Kh[(size_t)BH*S_LEN*RH];      // [bh][key][72] fp16, fragment-permuted
__device__ __half   g_Vt[(size_t)BH*S_LEN*RH];      // [bh][kt][d][72] fp16, fragment-permuted
__device__ uint32_t g_Eh[(size_t)BH*S_LEN*S_LEN/2]; // packed-half2 e scratch
__device__ int      g_mask_kind;      // 0 = 1B/elem, 1 = 4B/elem

__global__ void detect_mask_kind(const unsigned char* __restrict__ m) {
    __shared__ int s_big, s_off;
    if (threadIdx.x == 0) { s_big = 0; s_off = 0; }
    __syncthreads();
    int big = 0, off = 0;
    for (int base = threadIdx.x * 16; base < 4096; base += 256 * 16) {
        uint4 v = *(const uint4*)(m + base);
        unsigned int w[4] = {v.x, v.y, v.z, v.w};
#pragma unroll
        for (int j = 0; j < 4; j++)
#pragma unroll
            for (int b = 0; b < 4; b++) {
                unsigned int byte = (w[j] >> (8 * b)) & 0xFFu;
                if (byte > 1u) big = 1;
                if (byte != 0u && (((base + 4 * j + b) & 3) != 0)) off = 1;
            }
    }
    if (big) atomicOr(&s_big, 1);
    if (off) atomicOr(&s_off, 1);
    __syncthreads();
    if (threadIdx.x == 0) g_mask_kind = (s_big || !s_off) ? 1 : 0;
}

// fallback only (byte masks): widen u8 -> int32 into the attn buffer (same offsets).
__global__ void widen_mask_u8(const unsigned char* __restrict__ M, int* __restrict__ dst) {
    if (g_mask_kind != 0) return;
    const size_t n = (size_t)BH * S_LEN * S_LEN / 4;
    size_t i = (size_t)blockIdx.x * blockDim.x + threadIdx.x;
    const size_t stride = (size_t)gridDim.x * blockDim.x;
    for (; i < n; i += stride) {
        uchar4 v = ((const uchar4*)M)[i];
        ((int4*)dst)[i] = make_int4(v.x, v.y, v.z, v.w);
    }
}

// fragment permutation: position p = t*8 + 2*kc + h holds source word 8*kc + t + 4*h
__device__ __forceinline__ int frag_pos(int w) {
    int kc = w >> 3, rem = w & 7;
    int h = rem >> 2, t = rem & 3;
    return t * 8 + 2 * kc + h;
}

// fused prepass: K -> fp16 fragment-permuted rows; V -> fp16 per-tile transposed
__global__ void prep_kv(const float* __restrict__ K, const float* __restrict__ V) {
    __shared__ float vs[KT][D_DIM + 1];
    const int kt = blockIdx.x, bh = blockIdx.y;
    const int tid = threadIdx.x;
    const size_t row0 = (size_t)bh * S_LEN + kt * KT;

    {
        const float* ksrc = K + row0 * D_DIM;
        __half2* kdst = (__half2*)(g_Kh + row0 * RH);
        for (int i = tid; i < KT * 32; i += NTHREADS) {
            int r = i >> 5, w = i & 31;
            float2 v = *(const float2*)(ksrc + r * D_DIM + 2 * w);
            kdst[r * 36 + frag_pos(w)] = __floats2half2_rn(v.x, v.y);
        }
    }

    const float* src = V + row0 * D_DIM;
    for (int i = tid * 4; i < KT * D_DIM; i += NTHREADS * 4) {
        float4 v = *(const float4*)(src + i);
        int r = i >> 6, c = i & 63;
        vs[r][c] = v.x; vs[r][c+1] = v.y; vs[r][c+2] = v.z; vs[r][c+3] = v.w;
    }
    __syncthreads();
    __half2* dst = (__half2*)(g_Vt + ((size_t)bh * NT + kt) * (KT * RH));
    for (int i = tid; i < KT * 32; i += NTHREADS) {
        int d = i >> 5, kp = i & 31;
        dst[d * 36 + frag_pos(kp)] = __floats2half2_rn(vs[2*kp][d], vs[2*kp+1][d]);
    }
}

__device__ __forceinline__ void mma_f16(float c[4],
                                        uint32_t a0, uint32_t a1, uint32_t a2, uint32_t a3,
                                        uint32_t b0, uint32_t b1) {
    asm volatile(
        "mma.sync.aligned.m16n8k16.row.col.f32.f16.f16.f32 "
        "{%0,%1,%2,%3}, {%4,%5,%6,%7}, {%8,%9}, {%0,%1,%2,%3};\n"
        : "+f"(c[0]), "+f"(c[1]), "+f"(c[2]), "+f"(c[3])
        : "r"(a0), "r"(a1), "r"(a2), "r"(a3), "r"(b0), "r"(b1));
}

__device__ __forceinline__ uint32_t pack_h2(float lo, float hi) {
    __half2 h = __floats2half2_rn(lo, hi);
    return *(uint32_t*)&h;
}

__device__ __forceinline__ void mbar_init(uint32_t mbar, uint32_t count) {
    asm volatile("mbarrier.init.shared.b64 [%0], %1;" :: "r"(mbar), "r"(count) : "memory");
}
__device__ __forceinline__ void mbar_expect_tx(uint32_t mbar, uint32_t bytes) {
    asm volatile("mbarrier.arrive.expect_tx.shared.b64 _, [%0], %1;"
                 :: "r"(mbar), "r"(bytes) : "memory");
}
__device__ __forceinline__ void bulk_g2s(uint32_t dst, const void* src, uint32_t bytes, uint32_t mbar) {
    asm volatile("cp.async.bulk.shared::cluster.global.mbarrier::complete_tx::bytes "
                 "[%0], [%1], %2, [%3];"
                 :: "r"(dst), "l"(src), "r"(bytes), "r"(mbar) : "memory");
}
__device__ __forceinline__ void bulk_g2s_ef(uint32_t dst, const void* src, uint32_t bytes,
                                            uint32_t mbar, uint64_t pol) {
    asm volatile("cp.async.bulk.shared::cluster.global.mbarrier::complete_tx::bytes.L2::cache_hint "
                 "[%0], [%1], %2, [%3], %4;"
                 :: "r"(dst), "l"(src), "r"(bytes), "r"(mbar), "l"(pol) : "memory");
}
__device__ __forceinline__ void mbar_wait(uint32_t mbar, uint32_t parity) {
    asm volatile(
        "{\n\t.reg .pred P1;\n\t"
        "WAIT_%=:\n\t"
        "mbarrier.try_wait.parity.shared.b64 P1, [%0], %1;\n\t"
        "@P1 bra DONE_%=;\n\t"
        "bra WAIT_%=;\n\t"
        "DONE_%=:\n\t}"
        :: "r"(mbar), "r"(parity) : "memory");
}
__device__ __forceinline__ void stg_el(uint4* p, uint4 v, uint64_t pol) {
    asm volatile("st.global.L2::cache_hint.v4.b32 [%0], {%1,%2,%3,%4}, %5;"
                 :: "l"(p), "r"(v.x), "r"(v.y), "r"(v.z), "r"(v.w), "l"(pol) : "memory");
}
__device__ __forceinline__ uint4 ldg_lu(const uint4* p) {
    uint4 v;
    asm volatile("ld.global.lu.v4.b32 {%0,%1,%2,%3}, [%4];"
                 : "=r"(v.x), "=r"(v.y), "=r"(v.z), "=r"(v.w) : "l"(p));
    return v;
}
__device__ __forceinline__ void stg_cs_f4(float* p, float4 v) {
    asm volatile("st.global.cs.v4.f32 [%0], {%1,%2,%3,%4};"
                 :: "l"(p), "f"(v.x), "f"(v.y), "f"(v.z), "f"(v.w) : "memory");
}

__global__ void __launch_bounds__(NTHREADS, 2)
sdpa_main(const float* __restrict__ Q, const unsigned char* __restrict__ M,
          float* __restrict__ ctx, float* __restrict__ attn) {
    extern __shared__ __half smh[];
    uint32_t smb;
    asm("{ .reg .u64 tmp; cvta.to.shared.u64 tmp, %1; cvt.u32.u64 %0, tmp; }"
        : "=r"(smb) : "l"(smh));

    uint64_t polEF, polEL;
    asm("createpolicy.fractional.L2::evict_first.b64 %0, 1.0;" : "=l"(polEF));
    asm("createpolicy.fractional.L2::evict_last.b64 %0, 1.0;"  : "=l"(polEL));

    const int qb = blockIdx.x;            // 0..15
    const int bh = blockIdx.y;            // 0..63
    const size_t mrow0 = (size_t)bh * S_LEN + qb * M_BLK;

    const int tid = threadIdx.x, warp = tid >> 5, lane = tid & 31;
    const int g = lane >> 2, t = lane & 3;
    const int r0 = 16 * warp;

    const int* msrc = (g_mask_kind != 0) ? (const int*)M : (const int*)attn;
    const __half* gK = g_Kh + (size_t)bh * S_LEN * RH;
    const __half* gV = g_Vt + (size_t)bh * S_LEN * RH;

    if (tid == 0) {
        mbar_init(smb + OFF_MB, 1);
        mbar_init(smb + OFF_MB + 8, 1);
        asm volatile("fence.proxy.async.shared::cta;" ::: "memory");
    }
    __syncthreads();

    // producer: mask rows get evict_first (stream); K/V default (L2 reuse across 16 CTAs/bh)
    auto issue_tile = [&](int stage, int tile) {
        uint32_t mbar = smb + OFF_MB + stage * 8;
        if (tid == 0) mbar_expect_tx(mbar, TX_BYTES);
        if (tid < 128) {
            bulk_g2s_ef(smb + OFF_M + stage * MTILE_B + tid * 272,
                        msrc + (mrow0 + tid) * S_LEN + tile * KT, 256, mbar, polEF);
        } else if (tid == 128) {
            bulk_g2s(smb + OFF_K + stage * KTILE_B, gK + (size_t)tile * KT * RH, KTILE_B, mbar);
        } else if (tid == 129) {
            bulk_g2s(smb + OFF_V + stage * KTILE_B, gV + (size_t)tile * KT * RH, KTILE_B, mbar);
        }
    };

    // ---- Q fragments straight from gmem (once) ----
    uint32_t qa[4][4];
    {
        const float* Qp = Q + mrow0 * D_DIM;
#pragma unroll
        for (int kc = 0; kc < 4; kc++) {
            float2 v0 = *(const float2*)(Qp + (r0 + g)     * D_DIM + 16 * kc + 2 * t);
            float2 v1 = *(const float2*)(Qp + (r0 + g + 8) * D_DIM + 16 * kc + 2 * t);
            float2 v2 = *(const float2*)(Qp + (r0 + g)     * D_DIM + 16 * kc + 2 * t + 8);
            float2 v3 = *(const float2*)(Qp + (r0 + g + 8) * D_DIM + 16 * kc + 2 * t + 8);
            qa[kc][0] = pack_h2(v0.x, v0.y);
            qa[kc][1] = pack_h2(v1.x, v1.y);
            qa[kc][2] = pack_h2(v2.x, v2.y);
            qa[kc][3] = pack_h2(v3.x, v3.y);
        }
    }

    issue_tile(0, 0);
    issue_tile(1, 1);

    const size_t tb_warp = (((size_t)(bh * 16 + qb) * 8 + warp) * 32) * 512;

    float acc[8][4] = {};
    float rs0 = 0.f, rs1 = 0.f;

    for (int kt = 0; kt < NT; kt++) {
        const int cur = kt & 1;
        mbar_wait(smb + OFF_MB + cur * 8, (kt >> 1) & 1);

        const uint32_t* Kw = (const uint32_t*)(smh + (OFF_K + cur * KTILE_B) / 2);
        const uint32_t* Vw = (const uint32_t*)(smh + (OFF_V + cur * KTILE_B) / 2);
        const int*      Mb = (const int*)(smh + (OFF_M + cur * MTILE_B) / 2);

        // ---- QK (nb-outer): 2 LDS.128 + 4 mma per nb ----
        uint32_t pw[16];
        const float scale = 0.125f;
#pragma unroll
        for (int nb = 0; nb < 8; nb++) {
            const uint32_t* rowp = Kw + (8 * nb + g) * 36 + t * 8;
            uint4 k0 = *(const uint4*)rowp;
            uint4 k1 = *(const uint4*)(rowp + 4);
            float cl[4] = {};
            mma_f16(cl, qa[0][0], qa[0][1], qa[0][2], qa[0][3], k0.x, k0.y);
            mma_f16(cl, qa[1][0], qa[1][1], qa[1][2], qa[1][3], k0.z, k0.w);
            mma_f16(cl, qa[2][0], qa[2][1], qa[2][2], qa[2][3], k1.x, k1.y);
            mma_f16(cl, qa[3][0], qa[3][1], qa[3][2], qa[3][3], k1.z, k1.w);

            int2 ma = *(const int2*)&Mb[(r0 + g)     * MSTR + 8 * nb + 2 * t];
            int2 mb = *(const int2*)&Mb[(r0 + g + 8) * MSTR + 8 * nb + 2 * t];
            float e0 = ma.x ? 0.f : __expf(cl[0] * scale);
            float e1 = ma.y ? 0.f : __expf(cl[1] * scale);
            float e2 = mb.x ? 0.f : __expf(cl[2] * scale);
            float e3 = mb.y ? 0.f : __expf(cl[3] * scale);
            rs0 += e0 + e1; rs1 += e2 + e3;
            pw[2 * nb]     = pack_h2(e0, e1);
            pw[2 * nb + 1] = pack_h2(e2, e3);
        }

        // ---- scratch store: 4 x STG.128 with L2 evict_last ----
        {
            uint4* sp4 = (uint4*)(g_Eh + tb_warp + (size_t)kt * 512);
#pragma unroll
            for (int w4 = 0; w4 < 4; w4++)
                stg_el(sp4 + w4 * 32 + lane,
                       make_uint4(pw[4*w4], pw[4*w4+1], pw[4*w4+2], pw[4*w4+3]), polEL);
        }

        // ---- PV: 2 LDS.128 + 4 mma per db ----
#pragma unroll
        for (int db = 0; db < 8; db++) {
            const uint32_t* rowp = Vw + (8 * db + g) * 36 + t * 8;
            uint4 v0 = *(const uint4*)rowp;
            uint4 v1 = *(const uint4*)(rowp + 4);
            mma_f16(acc[db], pw[0],  pw[1],  pw[2],  pw[3],  v0.x, v0.y);
            mma_f16(acc[db], pw[4],  pw[5],  pw[6],  pw[7],  v0.z, v0.w);
            mma_f16(acc[db], pw[8],  pw[9],  pw[10], pw[11], v1.x, v1.y);
            mma_f16(acc[db], pw[12], pw[13], pw[14], pw[15], v1.z, v1.w);
        }

        __syncthreads();
        if (kt + 2 < NT) issue_tile(cur, kt + 2);
    }

    // ---- rowsums -> 1/Z ----
    rs0 += __shfl_xor_sync(0xFFFFFFFFu, rs0, 1);
    rs0 += __shfl_xor_sync(0xFFFFFFFFu, rs0, 2);
    rs1 += __shfl_xor_sync(0xFFFFFFFFu, rs1, 1);
    rs1 += __shfl_xor_sync(0xFFFFFFFFu, rs1, 2);
    const float iv0 = 1.f / rs0, iv1 = 1.f / rs1;

    // ---- context = acc / Z ----
    {
        float* cpa = ctx + (mrow0 + r0 + g) * D_DIM + 2 * t;
        float* cpb = cpa + 8 * D_DIM;
#pragma unroll
        for (int db = 0; db < 8; db++) {
            *(float2*)(cpa + 8 * db) = make_float2(acc[db][0] * iv0, acc[db][1] * iv0);
            *(float2*)(cpb + 8 * db) = make_float2(acc[db][2] * iv1, acc[db][3] * iv1);
        }
    }

    // ---- expand: scratch -> normalized fp32 attn; double-buffered staging +
    //      1-tile register prefetch of scratch reads (ld.global.lu) ----
    __syncthreads();
    uint32_t* stg0 = (uint32_t*)smh;              // 2 x (8 warps x 544 words)
    float* sinv = (float*)((uint32_t*)smh + 2 * 8 * 544);
    if (t == 0) {
        sinv[r0 + g]     = iv0;
        sinv[r0 + g + 8] = iv1;
    }
    __syncthreads();

    const size_t tb_cta = ((size_t)(bh * 16 + qb) * 8) * 32 * 512;
    const uint4* sbase = (const uint4*)(g_Eh + tb_cta);

    uint4 cur4[4];
#pragma unroll
    for (int w4 = 0; w4 < 4; w4++)
        cur4[w4] = ldg_lu(sbase + (size_t)(warp * 32 + 0) * 128 + w4 * 32 + lane);

    for (int kt = 0; kt < NT; kt++) {
        uint4 nxt4[4];
        if (kt + 1 < NT) {
#pragma unroll
            for (int w4 = 0; w4 < 4; w4++)
                nxt4[w4] = ldg_lu(sbase + (size_t)(warp * 32 + kt + 1) * 128 + w4 * 32 + lane);
        }

        uint32_t* stg = stg0 + (kt & 1) * (8 * 544);
#pragma unroll
        for (int w4 = 0; w4 < 4; w4++) {
            stg[warp * 544 + lane * 17 + 4 * w4 + 0] = cur4[w4].x;
            stg[warp * 544 + lane * 17 + 4 * w4 + 1] = cur4[w4].y;
            stg[warp * 544 + lane * 17 + 4 * w4 + 2] = cur4[w4].z;
            stg[warp * 544 + lane * 17 + 4 * w4 + 3] = cur4[w4].w;
        }
        __syncthreads();

#pragma unroll
        for (int it = 0; it < 8; it++) {
            int o = it * 256 + tid;
            int row = o >> 4;
            int cq  = o & 15;
            int wr = row >> 4, r = row & 15, gg = r & 7, p = r >> 3;
            int c0 = cq * 4;
            int nb = c0 >> 3;
            int t0 = (c0 & 7) >> 1;
            uint32_t w1 = stg[wr * 544 + (gg * 4 + t0)     * 17 + 2 * nb + p];
            uint32_t w2 = stg[wr * 544 + (gg * 4 + t0 + 1) * 17 + 2 * nb + p];
            float iv = sinv[row];
            __half2 h1 = *(__half2*)&w1, h2 = *(__half2*)&w2;
            float4 out = make_float4(__low2float(h1) * iv, __high2float(h1) * iv,
                                     __low2float(h2) * iv, __high2float(h2) * iv);
            stg_cs_f4(attn + (mrow0 + row) * S_LEN + kt * KT + c0, out);
        }

#pragma unroll
        for (int w4 = 0; w4 < 4; w4++) cur4[w4] = nxt4[w4];
    }
}

extern "C" void kernel_launch(void* const* d_in, const int* in_sizes, int n_in,
                              void* d_out, int out_size) {
    const float* Q = (const float*)d_in[0];
    const float* K = (const float*)d_in[1];
    const float* V = (const float*)d_in[2];
    const unsigned char* M = (const unsigned char*)d_in[3];

    float* ctx  = (float*)d_out;                          // [B,H,S,64]
    float* attn = ctx + (size_t)BH * S_LEN * D_DIM;       // [B,H,S,S]

    cudaFuncSetAttribute(sdpa_main,
                         cudaFuncAttributeMaxDynamicSharedMemorySize, SMEM_BYTES);

    detect_mask_kind<<<1, 256>>>(M);
    widen_mask_u8<<<4096, 256>>>(M, (int*)attn);   // no-op when mask is 4B/elem
    prep_kv<<<dim3(NT, BH), 256>>>(K, V);

    dim3 grid(S_LEN / M_BLK, BH);                         // 16 x 64 = 1024 CTAs
    sdpa_main<<<grid, NTHREADS, SMEM_BYTES>>>(Q, M, ctx, attn);
}